// round 12
// baseline (speedup 1.0000x reference)
#include <cuda_runtime.h>
#include <cuda_fp16.h>
#include <cuda_fp4.h>
#include <cstdint>

#define NROWS 100000
#define DCOLS 256
#define NEDGE 3200000

// ---------------- scratch (device globals: allocation-free) ----------------
__device__ __half  g_s16 [(size_t)NROWS * DCOLS];   // support fp16 (gather + output)
__device__ __half  g_h1  [(size_t)NROWS * DCOLS];   // A s fp16 (output term)
__device__ unsigned char g_h1q[(size_t)NROWS * DCOLS];      // h1 * 16  (e4m3, hop2 gather)
__device__ unsigned char g_h2q[(size_t)NROWS * DCOLS];      // h2 * 256 (e4m3, combine term)
__device__ unsigned char g_h2n[(size_t)NROWS * (DCOLS/2)];  // h2 * 256 (e2m1 fp4, hop3 gather)
__device__ int      g_counts[NROWS];
__device__ int      g_row_start[NROWS + 1];
__device__ int      g_cursor[NROWS];
__device__ unsigned g_csr[NEDGE];  // (col << 15) | (fp16 w bits sans sign)
__device__ int      g_blocksums[128];
__device__ int      g_blockoff[128];

// ======================= fp16 tensor-core GEMM =============================
#define GBM 128
#define GBN 128
#define GBK 32
#define HST 40   // padded smem stride (halves)

__global__ __launch_bounds__(256) void gemm_f16_kernel(
    const float* __restrict__ x, const float* __restrict__ w, int M)
{
    __shared__ __half As[GBM][HST];
    __shared__ __half Bs[GBN][HST];   // transposed: Bs[n][k]

    const int tid  = threadIdx.x;
    const int lane = tid & 31;
    const int warp = tid >> 5;
    const int gid  = lane >> 2;
    const int tig  = lane & 3;

    const int row0 = blockIdx.y * GBM;
    const int col0 = blockIdx.x * GBN;
    const int warp_m = (warp >> 2) * 64;
    const int warp_n = (warp & 3) * 32;

    int a_r[4], a_k[4], b_k[4], b_n[4];
#pragma unroll
    for (int h = 0; h < 4; h++) {
        const int idx = tid + h * 256;
        a_r[h] = idx >> 3;
        a_k[h] = (idx & 7) * 4;
        b_k[h] = idx >> 5;
        b_n[h] = (idx & 31) * 4;
    }

    float acc[4][4][4];
#pragma unroll
    for (int i = 0; i < 4; i++)
#pragma unroll
        for (int j = 0; j < 4; j++)
#pragma unroll
            for (int q = 0; q < 4; q++) acc[i][j][q] = 0.f;

    float4 ap[4], bp[4];
#pragma unroll
    for (int h = 0; h < 4; h++) {
        const int grow = row0 + a_r[h];
        ap[h] = make_float4(0.f, 0.f, 0.f, 0.f);
        if (grow < M)
            ap[h] = *(const float4*)(x + (size_t)grow * DCOLS + a_k[h]);
        bp[h] = *(const float4*)(w + (size_t)b_k[h] * DCOLS + col0 + b_n[h]);
    }

    for (int k0 = 0; k0 < DCOLS; k0 += GBK) {
#pragma unroll
        for (int h = 0; h < 4; h++) {
            *(__half2*)&As[a_r[h]][a_k[h]]     = __floats2half2_rn(ap[h].x, ap[h].y);
            *(__half2*)&As[a_r[h]][a_k[h] + 2] = __floats2half2_rn(ap[h].z, ap[h].w);
            Bs[b_n[h] + 0][b_k[h]] = __float2half_rn(bp[h].x);
            Bs[b_n[h] + 1][b_k[h]] = __float2half_rn(bp[h].y);
            Bs[b_n[h] + 2][b_k[h]] = __float2half_rn(bp[h].z);
            Bs[b_n[h] + 3][b_k[h]] = __float2half_rn(bp[h].w);
        }
        __syncthreads();

        const int kn = k0 + GBK;
        if (kn < DCOLS) {
#pragma unroll
            for (int h = 0; h < 4; h++) {
                const int grow = row0 + a_r[h];
                ap[h] = make_float4(0.f, 0.f, 0.f, 0.f);
                if (grow < M)
                    ap[h] = *(const float4*)(x + (size_t)grow * DCOLS + kn + a_k[h]);
                bp[h] = *(const float4*)(w + (size_t)(kn + b_k[h]) * DCOLS + col0 + b_n[h]);
            }
        }

#pragma unroll
        for (int ks = 0; ks < 2; ks++) {
            const int kk = ks * 16;
            unsigned a[4][4], b[4][2];
#pragma unroll
            for (int i = 0; i < 4; i++) {
                const int rm = warp_m + i * 16;
                a[i][0] = *(const unsigned*)&As[rm + gid    ][kk + 2 * tig];
                a[i][1] = *(const unsigned*)&As[rm + gid + 8][kk + 2 * tig];
                a[i][2] = *(const unsigned*)&As[rm + gid    ][kk + 8 + 2 * tig];
                a[i][3] = *(const unsigned*)&As[rm + gid + 8][kk + 8 + 2 * tig];
            }
#pragma unroll
            for (int j = 0; j < 4; j++) {
                const int n = warp_n + j * 8 + gid;
                b[j][0] = *(const unsigned*)&Bs[n][kk + 2 * tig];
                b[j][1] = *(const unsigned*)&Bs[n][kk + 8 + 2 * tig];
            }
#pragma unroll
            for (int i = 0; i < 4; i++)
#pragma unroll
                for (int j = 0; j < 4; j++) {
                    asm volatile(
                        "mma.sync.aligned.m16n8k16.row.col.f32.f16.f16.f32 "
                        "{%0,%1,%2,%3}, {%4,%5,%6,%7}, {%8,%9}, {%0,%1,%2,%3};"
                        : "+f"(acc[i][j][0]), "+f"(acc[i][j][1]),
                          "+f"(acc[i][j][2]), "+f"(acc[i][j][3])
                        : "r"(a[i][0]), "r"(a[i][1]), "r"(a[i][2]), "r"(a[i][3]),
                          "r"(b[j][0]), "r"(b[j][1]));
                }
        }
        __syncthreads();
    }

#pragma unroll
    for (int i = 0; i < 4; i++) {
#pragma unroll
        for (int h = 0; h < 2; h++) {
            const int r = row0 + warp_m + i * 16 + gid + h * 8;
            if (r < M) {
#pragma unroll
                for (int j = 0; j < 4; j++) {
                    const int c = col0 + warp_n + j * 8 + 2 * tig;
                    *(__half2*)(g_s16 + (size_t)r * DCOLS + c) =
                        __floats2half2_rn(acc[i][j][2 * h], acc[i][j][2 * h + 1]);
                }
            }
        }
    }
}

// ======================= CSR build =========================================
__global__ void zero_counts_kernel(int M)
{
    for (int i = blockIdx.x * blockDim.x + threadIdx.x; i < M;
         i += gridDim.x * blockDim.x)
        g_counts[i] = 0;
}

__global__ void count_kernel(const int* __restrict__ erow, int E)
{
    const int n4 = E >> 2;
    const int stride = gridDim.x * blockDim.x;
    const int t0 = blockIdx.x * blockDim.x + threadIdx.x;
    for (int i = t0; i < n4; i += stride) {
        int4 r = ((const int4*)erow)[i];
        atomicAdd(&g_counts[r.x], 1);
        atomicAdd(&g_counts[r.y], 1);
        atomicAdd(&g_counts[r.z], 1);
        atomicAdd(&g_counts[r.w], 1);
    }
    if (t0 < (E & 3))
        atomicAdd(&g_counts[erow[(n4 << 2) + t0]], 1);
}

__global__ __launch_bounds__(1024) void local_scan_kernel(int M)
{
    __shared__ int sh[1024];
    const int t = threadIdx.x;
    const int i = blockIdx.x * 1024 + t;
    const int v = (i < M) ? g_counts[i] : 0;
    sh[t] = v;
    __syncthreads();
#pragma unroll
    for (int d = 1; d < 1024; d <<= 1) {
        int u = (t >= d) ? sh[t - d] : 0;
        __syncthreads();
        sh[t] += u;
        __syncthreads();
    }
    if (i < M) g_row_start[i] = sh[t] - v;
    if (t == 1023) g_blocksums[blockIdx.x] = sh[1023];
}

__global__ __launch_bounds__(128) void scan_sums_kernel(int NB)
{
    __shared__ int sh[128];
    const int t = threadIdx.x;
    const int v = (t < NB) ? g_blocksums[t] : 0;
    sh[t] = v;
    __syncthreads();
#pragma unroll
    for (int d = 1; d < 128; d <<= 1) {
        int u = (t >= d) ? sh[t - d] : 0;
        __syncthreads();
        sh[t] += u;
        __syncthreads();
    }
    g_blockoff[t] = sh[t] - v;
}

__global__ __launch_bounds__(1024) void add_off_kernel(int M, int E)
{
    const int t = threadIdx.x;
    const int i = blockIdx.x * 1024 + t;
    if (i < M) {
        const int rs = g_row_start[i] + g_blockoff[blockIdx.x];
        g_row_start[i] = rs;
        g_cursor[i] = rs;
    }
    if (blockIdx.x == 0 && t == 0) g_row_start[M] = E;
}

__device__ __forceinline__ unsigned pack_edge(int col, float w)
{
    unsigned short hb = __half_as_ushort(__float2half_rn(w));
    return ((unsigned)col << 15) | (unsigned)(hb & 0x7FFF);
}

__global__ void scatter_kernel(const int* __restrict__ erow,
                               const int* __restrict__ ecol,
                               const float* __restrict__ ew, int E)
{
    const int n4 = E >> 2;
    const int stride = gridDim.x * blockDim.x;
    const int t0 = blockIdx.x * blockDim.x + threadIdx.x;
    for (int i = t0; i < n4; i += stride) {
        int4   r4 = ((const int4*)erow)[i];
        int4   c4 = ((const int4*)ecol)[i];
        float4 w4 = ((const float4*)ew)[i];
        int p;
        p = atomicAdd(&g_cursor[r4.x], 1); g_csr[p] = pack_edge(c4.x, w4.x);
        p = atomicAdd(&g_cursor[r4.y], 1); g_csr[p] = pack_edge(c4.y, w4.y);
        p = atomicAdd(&g_cursor[r4.z], 1); g_csr[p] = pack_edge(c4.z, w4.z);
        p = atomicAdd(&g_cursor[r4.w], 1); g_csr[p] = pack_edge(c4.w, w4.w);
    }
    if (t0 < (E & 3)) {
        const int i = (n4 << 2) + t0;
        const int pos = atomicAdd(&g_cursor[erow[i]], 1);
        g_csr[pos] = pack_edge(ecol[i], ew[i]);
    }
}

// ======================= fp8 / fp4 / half helpers ==========================
__device__ __forceinline__ __half2 fp8x2_to_h2(unsigned short v)
{
    unsigned r;
    asm("cvt.rn.f16x2.e4m3x2 %0, %1;" : "=r"(r) : "h"(v));
    return *(__half2*)&r;
}

__device__ __forceinline__ unsigned short h2_to_fp8x2(__half2 h)
{
    unsigned short r;
    unsigned u = *(unsigned*)&h;
    asm("cvt.rn.satfinite.e4m3x2.f16x2 %0, %1;" : "=h"(r) : "r"(u));
    return r;
}

// fp4 e2m1 via official intrinsics (.b8 register class handled by the header)
__device__ __forceinline__ unsigned char f2_to_fp4x2(float lo, float hi)
{
    float2 f = make_float2(lo, hi);
    return (unsigned char)__nv_cvt_float2_to_fp4x2(f, __NV_E2M1, cudaRoundNearest);
}

__device__ __forceinline__ __half2 fp4x2_to_h2(unsigned char v)
{
    __half2_raw hr = __nv_cvt_fp4x2_to_halfraw2((__nv_fp4x2_storage_t)v, __NV_E2M1);
    return *(__half2*)&hr;
}

__device__ __forceinline__ int edge_col(unsigned word) { return (int)(word >> 15); }
__device__ __forceinline__ __half2 edge_w2(unsigned word)
{
    unsigned u = (word & 0x7FFFu) * 0x00010001u;
    return *(__half2*)&u;
}

__device__ __forceinline__ void acc_h16h(__half2* a, __half2 w2, uint4 v)
{
    const __half2* h = (const __half2*)&v;
#pragma unroll
    for (int q = 0; q < 4; q++)
        a[q] = __hfma2(w2, h[q], a[q]);
}

__device__ __forceinline__ void acc_q8h(__half2* a, __half2 w2, uint2 v)
{
    const unsigned short* p = (const unsigned short*)&v;
#pragma unroll
    for (int q = 0; q < 4; q++)
        a[q] = __hfma2(w2, fp8x2_to_h2(p[q]), a[q]);
}

// fp4 accumulate: one uint = 8 values (4 bytes, each e2m1x2)
__device__ __forceinline__ void acc_q4h(__half2* a, __half2 w2, unsigned v)
{
#pragma unroll
    for (int q = 0; q < 4; q++) {
        unsigned char b = (unsigned char)((v >> (8 * q)) & 0xFFu);
        a[q] = __hfma2(w2, fp4x2_to_h2(b), a[q]);
    }
}

__device__ __forceinline__ uint4 ldcs4u(const unsigned* p)
{
    uint4 r;
    asm("ld.global.cs.v4.b32 {%0,%1,%2,%3}, [%4];"
        : "=r"(r.x), "=r"(r.y), "=r"(r.z), "=r"(r.w) : "l"(p));
    return r;
}

__device__ __forceinline__ void stcs4(void* p, uint4 v)
{
    asm volatile("st.global.cs.v4.b32 [%0], {%1,%2,%3,%4};"
                 :: "l"(p), "r"(v.x), "r"(v.y), "r"(v.z), "r"(v.w));
}

// ======================= SpMM hops =========================================
// hop1: fp16 gather of s16; writes h1 fp16 (streamed) + h1q fp8(=h1*16)
__global__ __launch_bounds__(256) void spmm1_kernel(int M)
{
    const int warp = (blockIdx.x * blockDim.x + threadIdx.x) >> 5;
    if (warp >= M) return;
    const int lane = threadIdx.x & 31;
    const int s = g_row_start[warp];
    const int e = g_row_start[warp + 1];

    __half2 a[4];
#pragma unroll
    for (int q = 0; q < 4; q++) a[q] = __half2half2(__float2half(0.f));

    int j = s;
    while ((j & 3) && j < e) {
        unsigned c = g_csr[j];
        acc_h16h(a, edge_w2(c), ((const uint4*)(g_s16 + (size_t)edge_col(c) * DCOLS))[lane]);
        j++;
    }
    for (; j + 7 < e; j += 8) {
        uint4 p0 = ldcs4u(&g_csr[j]);
        uint4 p1 = ldcs4u(&g_csr[j + 4]);
        uint4 v0 = ((const uint4*)(g_s16 + (size_t)edge_col(p0.x) * DCOLS))[lane];
        uint4 v1 = ((const uint4*)(g_s16 + (size_t)edge_col(p0.y) * DCOLS))[lane];
        uint4 v2 = ((const uint4*)(g_s16 + (size_t)edge_col(p0.z) * DCOLS))[lane];
        uint4 v3 = ((const uint4*)(g_s16 + (size_t)edge_col(p0.w) * DCOLS))[lane];
        uint4 v4 = ((const uint4*)(g_s16 + (size_t)edge_col(p1.x) * DCOLS))[lane];
        uint4 v5 = ((const uint4*)(g_s16 + (size_t)edge_col(p1.y) * DCOLS))[lane];
        uint4 v6 = ((const uint4*)(g_s16 + (size_t)edge_col(p1.z) * DCOLS))[lane];
        uint4 v7 = ((const uint4*)(g_s16 + (size_t)edge_col(p1.w) * DCOLS))[lane];
        acc_h16h(a, edge_w2(p0.x), v0);
        acc_h16h(a, edge_w2(p0.y), v1);
        acc_h16h(a, edge_w2(p0.z), v2);
        acc_h16h(a, edge_w2(p0.w), v3);
        acc_h16h(a, edge_w2(p1.x), v4);
        acc_h16h(a, edge_w2(p1.y), v5);
        acc_h16h(a, edge_w2(p1.z), v6);
        acc_h16h(a, edge_w2(p1.w), v7);
    }
    for (; j < e; j++) {
        unsigned c = g_csr[j];
        acc_h16h(a, edge_w2(c), ((const uint4*)(g_s16 + (size_t)edge_col(c) * DCOLS))[lane]);
    }

    uint4 o;
    o.x = *(unsigned*)&a[0]; o.y = *(unsigned*)&a[1];
    o.z = *(unsigned*)&a[2]; o.w = *(unsigned*)&a[3];
    stcs4((uint4*)(g_h1 + (size_t)warp * DCOLS) + lane, o);

    const __half2 x16 = __half2half2(__float2half(16.f));
    ushort4 q8;
    q8.x = h2_to_fp8x2(__hmul2(a[0], x16));
    q8.y = h2_to_fp8x2(__hmul2(a[1], x16));
    q8.z = h2_to_fp8x2(__hmul2(a[2], x16));
    q8.w = h2_to_fp8x2(__hmul2(a[3], x16));
    ((ushort4*)(g_h1q + (size_t)warp * DCOLS))[lane] = q8;
}

// hop2: gathers h1q (fp8 = h1*16), accum a = 16*h2;
// writes h2q fp8(=h2*256) for combine + h2n fp4(=h2*256) for hop3 gather
__global__ __launch_bounds__(256) void spmm2_kernel(int M)
{
    const int warp = (blockIdx.x * blockDim.x + threadIdx.x) >> 5;
    if (warp >= M) return;
    const int lane = threadIdx.x & 31;
    const int s = g_row_start[warp];
    const int e = g_row_start[warp + 1];

    __half2 a[4];
#pragma unroll
    for (int q = 0; q < 4; q++) a[q] = __half2half2(__float2half(0.f));

    int j = s;
    while ((j & 3) && j < e) {
        unsigned c = g_csr[j];
        acc_q8h(a, edge_w2(c), ((const uint2*)(g_h1q + (size_t)edge_col(c) * DCOLS))[lane]);
        j++;
    }
    for (; j + 7 < e; j += 8) {
        uint4 p0 = ldcs4u(&g_csr[j]);
        uint4 p1 = ldcs4u(&g_csr[j + 4]);
        uint2 v0 = ((const uint2*)(g_h1q + (size_t)edge_col(p0.x) * DCOLS))[lane];
        uint2 v1 = ((const uint2*)(g_h1q + (size_t)edge_col(p0.y) * DCOLS))[lane];
        uint2 v2 = ((const uint2*)(g_h1q + (size_t)edge_col(p0.z) * DCOLS))[lane];
        uint2 v3 = ((const uint2*)(g_h1q + (size_t)edge_col(p0.w) * DCOLS))[lane];
        uint2 v4 = ((const uint2*)(g_h1q + (size_t)edge_col(p1.x) * DCOLS))[lane];
        uint2 v5 = ((const uint2*)(g_h1q + (size_t)edge_col(p1.y) * DCOLS))[lane];
        uint2 v6 = ((const uint2*)(g_h1q + (size_t)edge_col(p1.z) * DCOLS))[lane];
        uint2 v7 = ((const uint2*)(g_h1q + (size_t)edge_col(p1.w) * DCOLS))[lane];
        acc_q8h(a, edge_w2(p0.x), v0);
        acc_q8h(a, edge_w2(p0.y), v1);
        acc_q8h(a, edge_w2(p0.z), v2);
        acc_q8h(a, edge_w2(p0.w), v3);
        acc_q8h(a, edge_w2(p1.x), v4);
        acc_q8h(a, edge_w2(p1.y), v5);
        acc_q8h(a, edge_w2(p1.z), v6);
        acc_q8h(a, edge_w2(p1.w), v7);
    }
    for (; j < e; j++) {
        unsigned c = g_csr[j];
        acc_q8h(a, edge_w2(c), ((const uint2*)(g_h1q + (size_t)edge_col(c) * DCOLS))[lane]);
    }

    const __half2 x16 = __half2half2(__float2half(16.f));
    __half2 s0 = __hmul2(a[0], x16);   // = 256 * h2 values
    __half2 s1 = __hmul2(a[1], x16);
    __half2 s2 = __hmul2(a[2], x16);
    __half2 s3 = __hmul2(a[3], x16);

    ushort4 q8;
    q8.x = h2_to_fp8x2(s0);
    q8.y = h2_to_fp8x2(s1);
    q8.z = h2_to_fp8x2(s2);
    q8.w = h2_to_fp8x2(s3);
    ((ushort4*)(g_h2q + (size_t)warp * DCOLS))[lane] = q8;

    // fp4 pack: 8 values -> 4 bytes -> one uint
    float2 f0 = __half22float2(s0);
    float2 f1 = __half22float2(s1);
    float2 f2 = __half22float2(s2);
    float2 f3 = __half22float2(s3);
    unsigned b0 = f2_to_fp4x2(f0.x, f0.y);
    unsigned b1 = f2_to_fp4x2(f1.x, f1.y);
    unsigned b2 = f2_to_fp4x2(f2.x, f2.y);
    unsigned b3 = f2_to_fp4x2(f3.x, f3.y);
    ((unsigned*)(g_h2n + (size_t)warp * (DCOLS / 2)))[lane] =
        b0 | (b1 << 8) | (b2 << 16) | (b3 << 24);
}

// hop3 fused with combine: out = s16 + h1 + h2q/256 + (A*h2n)/256 + bias
__global__ __launch_bounds__(256) void spmm3_combine_kernel(
    float* __restrict__ out, const float* __restrict__ bias, int M)
{
    const int warp = (blockIdx.x * blockDim.x + threadIdx.x) >> 5;
    if (warp >= M) return;
    const int lane = threadIdx.x & 31;
    const int s = g_row_start[warp];
    const int e = g_row_start[warp + 1];

    __half2 a[4];
#pragma unroll
    for (int q = 0; q < 4; q++) a[q] = __half2half2(__float2half(0.f));

    int j = s;
    while ((j & 3) && j < e) {
        unsigned c = g_csr[j];
        acc_q4h(a, edge_w2(c), ((const unsigned*)(g_h2n + (size_t)edge_col(c) * (DCOLS / 2)))[lane]);
        j++;
    }
    for (; j + 7 < e; j += 8) {
        uint4 p0 = ldcs4u(&g_csr[j]);
        uint4 p1 = ldcs4u(&g_csr[j + 4]);
        unsigned v0 = ((const unsigned*)(g_h2n + (size_t)edge_col(p0.x) * (DCOLS / 2)))[lane];
        unsigned v1 = ((const unsigned*)(g_h2n + (size_t)edge_col(p0.y) * (DCOLS / 2)))[lane];
        unsigned v2 = ((const unsigned*)(g_h2n + (size_t)edge_col(p0.z) * (DCOLS / 2)))[lane];
        unsigned v3 = ((const unsigned*)(g_h2n + (size_t)edge_col(p0.w) * (DCOLS / 2)))[lane];
        unsigned v4 = ((const unsigned*)(g_h2n + (size_t)edge_col(p1.x) * (DCOLS / 2)))[lane];
        unsigned v5 = ((const unsigned*)(g_h2n + (size_t)edge_col(p1.y) * (DCOLS / 2)))[lane];
        unsigned v6 = ((const unsigned*)(g_h2n + (size_t)edge_col(p1.z) * (DCOLS / 2)))[lane];
        unsigned v7 = ((const unsigned*)(g_h2n + (size_t)edge_col(p1.w) * (DCOLS / 2)))[lane];
        acc_q4h(a, edge_w2(p0.x), v0);
        acc_q4h(a, edge_w2(p0.y), v1);
        acc_q4h(a, edge_w2(p0.z), v2);
        acc_q4h(a, edge_w2(p0.w), v3);
        acc_q4h(a, edge_w2(p1.x), v4);
        acc_q4h(a, edge_w2(p1.y), v5);
        acc_q4h(a, edge_w2(p1.z), v6);
        acc_q4h(a, edge_w2(p1.w), v7);
    }
    for (; j < e; j++) {
        unsigned c = g_csr[j];
        acc_q4h(a, edge_w2(c), ((const unsigned*)(g_h2n + (size_t)edge_col(c) * (DCOLS / 2)))[lane]);
    }

    const size_t o = (size_t)warp * DCOLS + lane * 8;
    float4 b0 = *(const float4*)(bias + lane * 8);
    float4 b1 = *(const float4*)(bias + lane * 8 + 4);
    uint4  us = ((const uint4*)(g_s16 + (size_t)warp * DCOLS))[lane];
    uint4  u1 = ((const uint4*)(g_h1 + (size_t)warp * DCOLS))[lane];
    uint2  u2 = ((const uint2*)(g_h2q + (size_t)warp * DCOLS))[lane];
    const __half2* hs = (const __half2*)&us;
    const __half2* h1 = (const __half2*)&u1;
    const unsigned short* q2 = (const unsigned short*)&u2;

    float r[8];
#pragma unroll
    for (int q = 0; q < 4; q++) {
        float2 fs = __half22float2(hs[q]);
        float2 f1 = __half22float2(h1[q]);
        float2 f2 = __half22float2(fp8x2_to_h2(q2[q]));   // = 256 * h2
        float2 f3 = __half22float2(a[q]);                 // = 256 * h3
        r[2 * q + 0] = fs.x + f1.x + (f2.x + f3.x) * (1.f / 256.f);
        r[2 * q + 1] = fs.y + f1.y + (f2.y + f3.y) * (1.f / 256.f);
    }
    float4 o0 = make_float4(r[0] + b0.x, r[1] + b0.y, r[2] + b0.z, r[3] + b0.w);
    float4 o1 = make_float4(r[4] + b1.x, r[5] + b1.y, r[6] + b1.z, r[7] + b1.w);
    stcs4(out + o,     *(uint4*)&o0);
    stcs4(out + o + 4, *(uint4*)&o1);
}

// ======================= launch ============================================
extern "C" void kernel_launch(void* const* d_in, const int* in_sizes, int n_in,
                              void* d_out, int out_size)
{
    const float* x    = (const float*)d_in[0];
    const float* w    = (const float*)d_in[1];
    const float* bias = (const float*)d_in[2];
    const float* ew   = (const float*)d_in[3];
    const int*   er   = (const int*)d_in[4];
    const int*   ec   = (const int*)d_in[5];
    float* out = (float*)d_out;

    const int M = in_sizes[0] / DCOLS;
    const int E = in_sizes[3];
    const int NB = (M + 1023) / 1024;

    cudaStream_t s2;
    cudaEvent_t eFork, eJoin;
    cudaStreamCreateWithFlags(&s2, cudaStreamNonBlocking);
    cudaEventCreateWithFlags(&eFork, cudaEventDisableTiming);
    cudaEventCreateWithFlags(&eJoin, cudaEventDisableTiming);

    cudaEventRecord(eFork, 0);
    cudaStreamWaitEvent(s2, eFork, 0);

    // main stream: fp16 tensor-core GEMM
    dim3 ggrid(DCOLS / GBN, (M + GBM - 1) / GBM);
    gemm_f16_kernel<<<ggrid, 256>>>(x, w, M);

    // side stream: CSR build
    zero_counts_kernel<<<(M + 255) / 256, 256, 0, s2>>>(M);
    count_kernel<<<2048, 256, 0, s2>>>(er, E);
    local_scan_kernel<<<NB, 1024, 0, s2>>>(M);
    scan_sums_kernel<<<1, 128, 0, s2>>>(NB);
    add_off_kernel<<<NB, 1024, 0, s2>>>(M, E);
    scatter_kernel<<<2048, 256, 0, s2>>>(er, ec, ew, E);

    cudaEventRecord(eJoin, s2);
    cudaStreamWaitEvent(0, eJoin, 0);

    // hops
    const int sblocks = (int)(((size_t)M * 32 + 255) / 256);
    spmm1_kernel<<<sblocks, 256>>>(M);
    spmm2_kernel<<<sblocks, 256>>>(M);
    spmm3_combine_kernel<<<sblocks, 256>>>(out, bias, M);

    cudaEventDestroy(eFork);
    cudaEventDestroy(eJoin);
    cudaStreamDestroy(s2);
}

// round 13
// speedup vs baseline: 1.3331x; 1.3331x over previous
#include <cuda_runtime.h>
#include <cuda_fp16.h>
#include <cstdint>

#define NROWS 100000
#define DCOLS 256
#define NEDGE 3200000

// ---------------- scratch (device globals: allocation-free) ----------------
__device__ __half  g_s16 [(size_t)NROWS * DCOLS];   // support fp16 (gather + output)
__device__ __half  g_h1  [(size_t)NROWS * DCOLS];   // A s fp16 (output term)
__device__ unsigned char g_h1q[(size_t)NROWS * DCOLS]; // h1 * 16  (e4m3, hop2 gather)
__device__ unsigned char g_h2q[(size_t)NROWS * DCOLS]; // h2 * 256 (e4m3, hop3 gather + output term)
__device__ int      g_counts[NROWS];
__device__ int      g_row_start[NROWS + 1];
__device__ int      g_cursor[NROWS];
__device__ unsigned g_csr[NEDGE];  // (col << 15) | (fp16 w bits sans sign)
__device__ int      g_blocksums[128];
__device__ int      g_blockoff[128];

// ======================= fp16 tensor-core GEMM =============================
#define GBM 128
#define GBN 128
#define GBK 32
#define HST 40   // padded smem stride (halves)

__global__ __launch_bounds__(256) void gemm_f16_kernel(
    const float* __restrict__ x, const float* __restrict__ w, int M)
{
    __shared__ __half As[GBM][HST];
    __shared__ __half Bs[GBN][HST];   // transposed: Bs[n][k]

    const int tid  = threadIdx.x;
    const int lane = tid & 31;
    const int warp = tid >> 5;
    const int gid  = lane >> 2;
    const int tig  = lane & 3;

    const int row0 = blockIdx.y * GBM;
    const int col0 = blockIdx.x * GBN;
    const int warp_m = (warp >> 2) * 64;
    const int warp_n = (warp & 3) * 32;

    int a_r[4], a_k[4], b_k[4], b_n[4];
#pragma unroll
    for (int h = 0; h < 4; h++) {
        const int idx = tid + h * 256;
        a_r[h] = idx >> 3;
        a_k[h] = (idx & 7) * 4;
        b_k[h] = idx >> 5;
        b_n[h] = (idx & 31) * 4;
    }

    float acc[4][4][4];
#pragma unroll
    for (int i = 0; i < 4; i++)
#pragma unroll
        for (int j = 0; j < 4; j++)
#pragma unroll
            for (int q = 0; q < 4; q++) acc[i][j][q] = 0.f;

    float4 ap[4], bp[4];
#pragma unroll
    for (int h = 0; h < 4; h++) {
        const int grow = row0 + a_r[h];
        ap[h] = make_float4(0.f, 0.f, 0.f, 0.f);
        if (grow < M)
            ap[h] = *(const float4*)(x + (size_t)grow * DCOLS + a_k[h]);
        bp[h] = *(const float4*)(w + (size_t)b_k[h] * DCOLS + col0 + b_n[h]);
    }

    for (int k0 = 0; k0 < DCOLS; k0 += GBK) {
#pragma unroll
        for (int h = 0; h < 4; h++) {
            *(__half2*)&As[a_r[h]][a_k[h]]     = __floats2half2_rn(ap[h].x, ap[h].y);
            *(__half2*)&As[a_r[h]][a_k[h] + 2] = __floats2half2_rn(ap[h].z, ap[h].w);
            Bs[b_n[h] + 0][b_k[h]] = __float2half_rn(bp[h].x);
            Bs[b_n[h] + 1][b_k[h]] = __float2half_rn(bp[h].y);
            Bs[b_n[h] + 2][b_k[h]] = __float2half_rn(bp[h].z);
            Bs[b_n[h] + 3][b_k[h]] = __float2half_rn(bp[h].w);
        }
        __syncthreads();

        const int kn = k0 + GBK;
        if (kn < DCOLS) {
#pragma unroll
            for (int h = 0; h < 4; h++) {
                const int grow = row0 + a_r[h];
                ap[h] = make_float4(0.f, 0.f, 0.f, 0.f);
                if (grow < M)
                    ap[h] = *(const float4*)(x + (size_t)grow * DCOLS + kn + a_k[h]);
                bp[h] = *(const float4*)(w + (size_t)(kn + b_k[h]) * DCOLS + col0 + b_n[h]);
            }
        }

#pragma unroll
        for (int ks = 0; ks < 2; ks++) {
            const int kk = ks * 16;
            unsigned a[4][4], b[4][2];
#pragma unroll
            for (int i = 0; i < 4; i++) {
                const int rm = warp_m + i * 16;
                a[i][0] = *(const unsigned*)&As[rm + gid    ][kk + 2 * tig];
                a[i][1] = *(const unsigned*)&As[rm + gid + 8][kk + 2 * tig];
                a[i][2] = *(const unsigned*)&As[rm + gid    ][kk + 8 + 2 * tig];
                a[i][3] = *(const unsigned*)&As[rm + gid + 8][kk + 8 + 2 * tig];
            }
#pragma unroll
            for (int j = 0; j < 4; j++) {
                const int n = warp_n + j * 8 + gid;
                b[j][0] = *(const unsigned*)&Bs[n][kk + 2 * tig];
                b[j][1] = *(const unsigned*)&Bs[n][kk + 8 + 2 * tig];
            }
#pragma unroll
            for (int i = 0; i < 4; i++)
#pragma unroll
                for (int j = 0; j < 4; j++) {
                    asm volatile(
                        "mma.sync.aligned.m16n8k16.row.col.f32.f16.f16.f32 "
                        "{%0,%1,%2,%3}, {%4,%5,%6,%7}, {%8,%9}, {%0,%1,%2,%3};"
                        : "+f"(acc[i][j][0]), "+f"(acc[i][j][1]),
                          "+f"(acc[i][j][2]), "+f"(acc[i][j][3])
                        : "r"(a[i][0]), "r"(a[i][1]), "r"(a[i][2]), "r"(a[i][3]),
                          "r"(b[j][0]), "r"(b[j][1]));
                }
        }
        __syncthreads();
    }

#pragma unroll
    for (int i = 0; i < 4; i++) {
#pragma unroll
        for (int h = 0; h < 2; h++) {
            const int r = row0 + warp_m + i * 16 + gid + h * 8;
            if (r < M) {
#pragma unroll
                for (int j = 0; j < 4; j++) {
                    const int c = col0 + warp_n + j * 8 + 2 * tig;
                    *(__half2*)(g_s16 + (size_t)r * DCOLS + c) =
                        __floats2half2_rn(acc[i][j][2 * h], acc[i][j][2 * h + 1]);
                }
            }
        }
    }
}

// ======================= CSR build =========================================
__global__ void zero_counts_kernel(int M)
{
    for (int i = blockIdx.x * blockDim.x + threadIdx.x; i < M;
         i += gridDim.x * blockDim.x)
        g_counts[i] = 0;
}

__global__ void count_kernel(const int* __restrict__ erow, int E)
{
    const int n4 = E >> 2;
    const int stride = gridDim.x * blockDim.x;
    const int t0 = blockIdx.x * blockDim.x + threadIdx.x;
    for (int i = t0; i < n4; i += stride) {
        int4 r = ((const int4*)erow)[i];
        atomicAdd(&g_counts[r.x], 1);
        atomicAdd(&g_counts[r.y], 1);
        atomicAdd(&g_counts[r.z], 1);
        atomicAdd(&g_counts[r.w], 1);
    }
    if (t0 < (E & 3))
        atomicAdd(&g_counts[erow[(n4 << 2) + t0]], 1);
}

__global__ __launch_bounds__(1024) void local_scan_kernel(int M)
{
    __shared__ int sh[1024];
    const int t = threadIdx.x;
    const int i = blockIdx.x * 1024 + t;
    const int v = (i < M) ? g_counts[i] : 0;
    sh[t] = v;
    __syncthreads();
#pragma unroll
    for (int d = 1; d < 1024; d <<= 1) {
        int u = (t >= d) ? sh[t - d] : 0;
        __syncthreads();
        sh[t] += u;
        __syncthreads();
    }
    if (i < M) g_row_start[i] = sh[t] - v;
    if (t == 1023) g_blocksums[blockIdx.x] = sh[1023];
}

__global__ __launch_bounds__(128) void scan_sums_kernel(int NB)
{
    __shared__ int sh[128];
    const int t = threadIdx.x;
    const int v = (t < NB) ? g_blocksums[t] : 0;
    sh[t] = v;
    __syncthreads();
#pragma unroll
    for (int d = 1; d < 128; d <<= 1) {
        int u = (t >= d) ? sh[t - d] : 0;
        __syncthreads();
        sh[t] += u;
        __syncthreads();
    }
    g_blockoff[t] = sh[t] - v;
}

__global__ __launch_bounds__(1024) void add_off_kernel(int M, int E)
{
    const int t = threadIdx.x;
    const int i = blockIdx.x * 1024 + t;
    if (i < M) {
        const int rs = g_row_start[i] + g_blockoff[blockIdx.x];
        g_row_start[i] = rs;
        g_cursor[i] = rs;
    }
    if (blockIdx.x == 0 && t == 0) g_row_start[M] = E;
}

__device__ __forceinline__ unsigned pack_edge(int col, float w)
{
    unsigned short hb = __half_as_ushort(__float2half_rn(w));
    return ((unsigned)col << 15) | (unsigned)(hb & 0x7FFF);
}

__global__ void scatter_kernel(const int* __restrict__ erow,
                               const int* __restrict__ ecol,
                               const float* __restrict__ ew, int E)
{
    const int n4 = E >> 2;
    const int stride = gridDim.x * blockDim.x;
    const int t0 = blockIdx.x * blockDim.x + threadIdx.x;
    for (int i = t0; i < n4; i += stride) {
        int4   r4 = ((const int4*)erow)[i];
        int4   c4 = ((const int4*)ecol)[i];
        float4 w4 = ((const float4*)ew)[i];
        int p;
        p = atomicAdd(&g_cursor[r4.x], 1); g_csr[p] = pack_edge(c4.x, w4.x);
        p = atomicAdd(&g_cursor[r4.y], 1); g_csr[p] = pack_edge(c4.y, w4.y);
        p = atomicAdd(&g_cursor[r4.z], 1); g_csr[p] = pack_edge(c4.z, w4.z);
        p = atomicAdd(&g_cursor[r4.w], 1); g_csr[p] = pack_edge(c4.w, w4.w);
    }
    if (t0 < (E & 3)) {
        const int i = (n4 << 2) + t0;
        const int pos = atomicAdd(&g_cursor[erow[i]], 1);
        g_csr[pos] = pack_edge(ecol[i], ew[i]);
    }
}

// ======================= fp8 / half helpers ================================
__device__ __forceinline__ __half2 fp8x2_to_h2(unsigned short v)
{
    unsigned r;
    asm("cvt.rn.f16x2.e4m3x2 %0, %1;" : "=r"(r) : "h"(v));
    return *(__half2*)&r;
}

__device__ __forceinline__ unsigned short h2_to_fp8x2(__half2 h)
{
    unsigned short r;
    unsigned u = *(unsigned*)&h;
    asm("cvt.rn.satfinite.e4m3x2.f16x2 %0, %1;" : "=h"(r) : "r"(u));
    return r;
}

__device__ __forceinline__ int edge_col(unsigned word) { return (int)(word >> 15); }
__device__ __forceinline__ __half2 edge_w2(unsigned word)
{
    unsigned u = (word & 0x7FFFu) * 0x00010001u;
    return *(__half2*)&u;
}

__device__ __forceinline__ void acc_h16h(__half2* a, __half2 w2, uint4 v)
{
    const __half2* h = (const __half2*)&v;
#pragma unroll
    for (int q = 0; q < 4; q++)
        a[q] = __hfma2(w2, h[q], a[q]);
}

__device__ __forceinline__ void acc_q8h(__half2* a, __half2 w2, uint2 v)
{
    const unsigned short* p = (const unsigned short*)&v;
#pragma unroll
    for (int q = 0; q < 4; q++)
        a[q] = __hfma2(w2, fp8x2_to_h2(p[q]), a[q]);
}

__device__ __forceinline__ uint4 ldcs4u(const unsigned* p)
{
    uint4 r;
    asm("ld.global.cs.v4.b32 {%0,%1,%2,%3}, [%4];"
        : "=r"(r.x), "=r"(r.y), "=r"(r.z), "=r"(r.w) : "l"(p));
    return r;
}

__device__ __forceinline__ void stcs4(void* p, uint4 v)
{
    asm volatile("st.global.cs.v4.b32 [%0], {%1,%2,%3,%4};"
                 :: "l"(p), "r"(v.x), "r"(v.y), "r"(v.z), "r"(v.w));
}

// ======================= SpMM hops =========================================
// hop1: fp16 gather of s16; writes h1 fp16 (streamed) + h1q fp8(=h1*16)
__global__ __launch_bounds__(256) void spmm1_kernel(int M)
{
    const int warp = (blockIdx.x * blockDim.x + threadIdx.x) >> 5;
    if (warp >= M) return;
    const int lane = threadIdx.x & 31;
    const int s = g_row_start[warp];
    const int e = g_row_start[warp + 1];

    __half2 a[4];
#pragma unroll
    for (int q = 0; q < 4; q++) a[q] = __half2half2(__float2half(0.f));

    int j = s;
    while ((j & 3) && j < e) {
        unsigned c = g_csr[j];
        acc_h16h(a, edge_w2(c), ((const uint4*)(g_s16 + (size_t)edge_col(c) * DCOLS))[lane]);
        j++;
    }
    for (; j + 7 < e; j += 8) {
        uint4 p0 = ldcs4u(&g_csr[j]);
        uint4 p1 = ldcs4u(&g_csr[j + 4]);
        uint4 v0 = ((const uint4*)(g_s16 + (size_t)edge_col(p0.x) * DCOLS))[lane];
        uint4 v1 = ((const uint4*)(g_s16 + (size_t)edge_col(p0.y) * DCOLS))[lane];
        uint4 v2 = ((const uint4*)(g_s16 + (size_t)edge_col(p0.z) * DCOLS))[lane];
        uint4 v3 = ((const uint4*)(g_s16 + (size_t)edge_col(p0.w) * DCOLS))[lane];
        uint4 v4 = ((const uint4*)(g_s16 + (size_t)edge_col(p1.x) * DCOLS))[lane];
        uint4 v5 = ((const uint4*)(g_s16 + (size_t)edge_col(p1.y) * DCOLS))[lane];
        uint4 v6 = ((const uint4*)(g_s16 + (size_t)edge_col(p1.z) * DCOLS))[lane];
        uint4 v7 = ((const uint4*)(g_s16 + (size_t)edge_col(p1.w) * DCOLS))[lane];
        acc_h16h(a, edge_w2(p0.x), v0);
        acc_h16h(a, edge_w2(p0.y), v1);
        acc_h16h(a, edge_w2(p0.z), v2);
        acc_h16h(a, edge_w2(p0.w), v3);
        acc_h16h(a, edge_w2(p1.x), v4);
        acc_h16h(a, edge_w2(p1.y), v5);
        acc_h16h(a, edge_w2(p1.z), v6);
        acc_h16h(a, edge_w2(p1.w), v7);
    }
    for (; j < e; j++) {
        unsigned c = g_csr[j];
        acc_h16h(a, edge_w2(c), ((const uint4*)(g_s16 + (size_t)edge_col(c) * DCOLS))[lane]);
    }

    uint4 o;
    o.x = *(unsigned*)&a[0]; o.y = *(unsigned*)&a[1];
    o.z = *(unsigned*)&a[2]; o.w = *(unsigned*)&a[3];
    stcs4((uint4*)(g_h1 + (size_t)warp * DCOLS) + lane, o);

    const __half2 x16 = __half2half2(__float2half(16.f));
    ushort4 q8;
    q8.x = h2_to_fp8x2(__hmul2(a[0], x16));
    q8.y = h2_to_fp8x2(__hmul2(a[1], x16));
    q8.z = h2_to_fp8x2(__hmul2(a[2], x16));
    q8.w = h2_to_fp8x2(__hmul2(a[3], x16));
    ((ushort4*)(g_h1q + (size_t)warp * DCOLS))[lane] = q8;
}

// hop2: gathers h1q (fp8 = h1*16), half2 accum (a = 16*h2);
// writes h2q fp8(=h2*256 = a*16) ONLY
__global__ __launch_bounds__(256) void spmm2_kernel(int M)
{
    const int warp = (blockIdx.x * blockDim.x + threadIdx.x) >> 5;
    if (warp >= M) return;
    const int lane = threadIdx.x & 31;
    const int s = g_row_start[warp];
    const int e = g_row_start[warp + 1];

    __half2 a[4];
#pragma unroll
    for (int q = 0; q < 4; q++) a[q] = __half2half2(__float2half(0.f));

    int j = s;
    while ((j & 3) && j < e) {
        unsigned c = g_csr[j];
        acc_q8h(a, edge_w2(c), ((const uint2*)(g_h1q + (size_t)edge_col(c) * DCOLS))[lane]);
        j++;
    }
    for (; j + 7 < e; j += 8) {
        uint4 p0 = ldcs4u(&g_csr[j]);
        uint4 p1 = ldcs4u(&g_csr[j + 4]);
        uint2 v0 = ((const uint2*)(g_h1q + (size_t)edge_col(p0.x) * DCOLS))[lane];
        uint2 v1 = ((const uint2*)(g_h1q + (size_t)edge_col(p0.y) * DCOLS))[lane];
        uint2 v2 = ((const uint2*)(g_h1q + (size_t)edge_col(p0.z) * DCOLS))[lane];
        uint2 v3 = ((const uint2*)(g_h1q + (size_t)edge_col(p0.w) * DCOLS))[lane];
        uint2 v4 = ((const uint2*)(g_h1q + (size_t)edge_col(p1.x) * DCOLS))[lane];
        uint2 v5 = ((const uint2*)(g_h1q + (size_t)edge_col(p1.y) * DCOLS))[lane];
        uint2 v6 = ((const uint2*)(g_h1q + (size_t)edge_col(p1.z) * DCOLS))[lane];
        uint2 v7 = ((const uint2*)(g_h1q + (size_t)edge_col(p1.w) * DCOLS))[lane];
        acc_q8h(a, edge_w2(p0.x), v0);
        acc_q8h(a, edge_w2(p0.y), v1);
        acc_q8h(a, edge_w2(p0.z), v2);
        acc_q8h(a, edge_w2(p0.w), v3);
        acc_q8h(a, edge_w2(p1.x), v4);
        acc_q8h(a, edge_w2(p1.y), v5);
        acc_q8h(a, edge_w2(p1.z), v6);
        acc_q8h(a, edge_w2(p1.w), v7);
    }
    for (; j < e; j++) {
        unsigned c = g_csr[j];
        acc_q8h(a, edge_w2(c), ((const uint2*)(g_h1q + (size_t)edge_col(c) * DCOLS))[lane]);
    }

    const __half2 x16 = __half2half2(__float2half(16.f));
    ushort4 q8;
    q8.x = h2_to_fp8x2(__hmul2(a[0], x16));
    q8.y = h2_to_fp8x2(__hmul2(a[1], x16));
    q8.z = h2_to_fp8x2(__hmul2(a[2], x16));
    q8.w = h2_to_fp8x2(__hmul2(a[3], x16));
    ((ushort4*)(g_h2q + (size_t)warp * DCOLS))[lane] = q8;
}

// hop3 fused with combine: out = s16 + h1 + h2q/256 + (A*h2q)/256 + bias
__global__ __launch_bounds__(256) void spmm3_combine_kernel(
    float* __restrict__ out, const float* __restrict__ bias, int M)
{
    const int warp = (blockIdx.x * blockDim.x + threadIdx.x) >> 5;
    if (warp >= M) return;
    const int lane = threadIdx.x & 31;
    const int s = g_row_start[warp];
    const int e = g_row_start[warp + 1];

    // prefetch combine terms (addresses independent of gather loop) — in
    // flight behind the gathers, consumed after the loop
    float4 b0 = *(const float4*)(bias + lane * 8);
    float4 b1 = *(const float4*)(bias + lane * 8 + 4);
    uint4  us = ((const uint4*)(g_s16 + (size_t)warp * DCOLS))[lane];
    uint4  u1 = ((const uint4*)(g_h1 + (size_t)warp * DCOLS))[lane];
    uint2  u2 = ((const uint2*)(g_h2q + (size_t)warp * DCOLS))[lane];

    __half2 a[4];
#pragma unroll
    for (int q = 0; q < 4; q++) a[q] = __half2half2(__float2half(0.f));

    int j = s;
    while ((j & 3) && j < e) {
        unsigned c = g_csr[j];
        acc_q8h(a, edge_w2(c), ((const uint2*)(g_h2q + (size_t)edge_col(c) * DCOLS))[lane]);
        j++;
    }
    for (; j + 7 < e; j += 8) {
        uint4 p0 = ldcs4u(&g_csr[j]);
        uint4 p1 = ldcs4u(&g_csr[j + 4]);
        uint2 v0 = ((const uint2*)(g_h2q + (size_t)edge_col(p0.x) * DCOLS))[lane];
        uint2 v1 = ((const uint2*)(g_h2q + (size_t)edge_col(p0.y) * DCOLS))[lane];
        uint2 v2 = ((const uint2*)(g_h2q + (size_t)edge_col(p0.z) * DCOLS))[lane];
        uint2 v3 = ((const uint2*)(g_h2q + (size_t)edge_col(p0.w) * DCOLS))[lane];
        uint2 v4 = ((const uint2*)(g_h2q + (size_t)edge_col(p1.x) * DCOLS))[lane];
        uint2 v5 = ((const uint2*)(g_h2q + (size_t)edge_col(p1.y) * DCOLS))[lane];
        uint2 v6 = ((const uint2*)(g_h2q + (size_t)edge_col(p1.z) * DCOLS))[lane];
        uint2 v7 = ((const uint2*)(g_h2q + (size_t)edge_col(p1.w) * DCOLS))[lane];
        acc_q8h(a, edge_w2(p0.x), v0);
        acc_q8h(a, edge_w2(p0.y), v1);
        acc_q8h(a, edge_w2(p0.z), v2);
        acc_q8h(a, edge_w2(p0.w), v3);
        acc_q8h(a, edge_w2(p1.x), v4);
        acc_q8h(a, edge_w2(p1.y), v5);
        acc_q8h(a, edge_w2(p1.z), v6);
        acc_q8h(a, edge_w2(p1.w), v7);
    }
    for (; j < e; j++) {
        unsigned c = g_csr[j];
        acc_q8h(a, edge_w2(c), ((const uint2*)(g_h2q + (size_t)edge_col(c) * DCOLS))[lane]);
    }

    const size_t o = (size_t)warp * DCOLS + lane * 8;
    const __half2* hs = (const __half2*)&us;
    const __half2* h1 = (const __half2*)&u1;
    const unsigned short* q2 = (const unsigned short*)&u2;

    float r[8];
#pragma unroll
    for (int q = 0; q < 4; q++) {
        float2 fs = __half22float2(hs[q]);
        float2 f1 = __half22float2(h1[q]);
        float2 f2 = __half22float2(fp8x2_to_h2(q2[q]));   // = 256 * h2
        float2 f3 = __half22float2(a[q]);                 // = 256 * h3
        r[2 * q + 0] = fs.x + f1.x + (f2.x + f3.x) * (1.f / 256.f);
        r[2 * q + 1] = fs.y + f1.y + (f2.y + f3.y) * (1.f / 256.f);
    }
    float4 o0 = make_float4(r[0] + b0.x, r[1] + b0.y, r[2] + b0.z, r[3] + b0.w);
    float4 o1 = make_float4(r[4] + b1.x, r[5] + b1.y, r[6] + b1.z, r[7] + b1.w);
    stcs4(out + o,     *(uint4*)&o0);
    stcs4(out + o + 4, *(uint4*)&o1);
}

// ======================= launch ============================================
extern "C" void kernel_launch(void* const* d_in, const int* in_sizes, int n_in,
                              void* d_out, int out_size)
{
    const float* x    = (const float*)d_in[0];
    const float* w    = (const float*)d_in[1];
    const float* bias = (const float*)d_in[2];
    const float* ew   = (const float*)d_in[3];
    const int*   er   = (const int*)d_in[4];
    const int*   ec   = (const int*)d_in[5];
    float* out = (float*)d_out;

    const int M = in_sizes[0] / DCOLS;
    const int E = in_sizes[3];
    const int NB = (M + 1023) / 1024;

    cudaStream_t s2;
    cudaEvent_t eFork, eJoin;
    cudaStreamCreateWithFlags(&s2, cudaStreamNonBlocking);
    cudaEventCreateWithFlags(&eFork, cudaEventDisableTiming);
    cudaEventCreateWithFlags(&eJoin, cudaEventDisableTiming);

    cudaEventRecord(eFork, 0);
    cudaStreamWaitEvent(s2, eFork, 0);

    // main stream: fp16 tensor-core GEMM
    dim3 ggrid(DCOLS / GBN, (M + GBM - 1) / GBM);
    gemm_f16_kernel<<<ggrid, 256>>>(x, w, M);

    // side stream: CSR build
    zero_counts_kernel<<<(M + 255) / 256, 256, 0, s2>>>(M);
    count_kernel<<<1024, 256, 0, s2>>>(er, E);
    local_scan_kernel<<<NB, 1024, 0, s2>>>(M);
    scan_sums_kernel<<<1, 128, 0, s2>>>(NB);
    add_off_kernel<<<NB, 1024, 0, s2>>>(M, E);
    scatter_kernel<<<1024, 256, 0, s2>>>(er, ec, ew, E);

    cudaEventRecord(eJoin, s2);
    cudaStreamWaitEvent(0, eJoin, 0);

    // hops
    const int sblocks = (int)(((size_t)M * 32 + 255) / 256);
    spmm1_kernel<<<sblocks, 256>>>(M);
    spmm2_kernel<<<sblocks, 256>>>(M);
    spmm3_combine_kernel<<<sblocks, 256>>>(out, bias, M);

    cudaEventDestroy(eFork);
    cudaEventDestroy(eJoin);
    cudaStreamDestroy(s2);
}

// round 14
// speedup vs baseline: 1.5432x; 1.1576x over previous
#include <cuda_runtime.h>
#include <cuda_fp16.h>
#include <cstdint>

#define NROWS 100000
#define DCOLS 256
#define NEDGE 3200000

// ---------------- scratch (device globals: allocation-free) ----------------
__device__ __half  g_s16 [(size_t)NROWS * DCOLS];   // support fp16 (gather + output)
__device__ __half  g_h1  [(size_t)NROWS * DCOLS];   // A s fp16 (output term)
__device__ unsigned char g_h1q[(size_t)NROWS * DCOLS]; // h1 * 16  (e4m3, hop2 gather)
__device__ unsigned char g_h2q[(size_t)NROWS * DCOLS]; // h2 * 256 (e4m3, hop3 gather + output term)
__device__ int      g_counts[NROWS];
__device__ int      g_row_start[NROWS + 1];
__device__ int      g_cursor[NROWS];
__device__ unsigned g_csr[NEDGE];  // (col << 15) | (fp16 w bits sans sign)
__device__ int      g_blocksums[128];
__device__ int      g_blockoff[128];

// ======================= fp16 tensor-core GEMM =============================
#define GBM 128
#define GBN 128
#define GBK 32
#define HST 40   // padded smem stride (halves)

__global__ __launch_bounds__(256) void gemm_f16_kernel(
    const float* __restrict__ x, const float* __restrict__ w, int M)
{
    __shared__ __half As[GBM][HST];
    __shared__ __half Bs[GBN][HST];   // transposed: Bs[n][k]

    const int tid  = threadIdx.x;
    const int lane = tid & 31;
    const int warp = tid >> 5;
    const int gid  = lane >> 2;
    const int tig  = lane & 3;

    const int row0 = blockIdx.y * GBM;
    const int col0 = blockIdx.x * GBN;
    const int warp_m = (warp >> 2) * 64;
    const int warp_n = (warp & 3) * 32;

    int a_r[4], a_k[4], b_k[4], b_n[4];
#pragma unroll
    for (int h = 0; h < 4; h++) {
        const int idx = tid + h * 256;
        a_r[h] = idx >> 3;
        a_k[h] = (idx & 7) * 4;
        b_k[h] = idx >> 5;
        b_n[h] = (idx & 31) * 4;
    }

    float acc[4][4][4];
#pragma unroll
    for (int i = 0; i < 4; i++)
#pragma unroll
        for (int j = 0; j < 4; j++)
#pragma unroll
            for (int q = 0; q < 4; q++) acc[i][j][q] = 0.f;

    float4 ap[4], bp[4];
#pragma unroll
    for (int h = 0; h < 4; h++) {
        const int grow = row0 + a_r[h];
        ap[h] = make_float4(0.f, 0.f, 0.f, 0.f);
        if (grow < M)
            ap[h] = *(const float4*)(x + (size_t)grow * DCOLS + a_k[h]);
        bp[h] = *(const float4*)(w + (size_t)b_k[h] * DCOLS + col0 + b_n[h]);
    }

    for (int k0 = 0; k0 < DCOLS; k0 += GBK) {
#pragma unroll
        for (int h = 0; h < 4; h++) {
            *(__half2*)&As[a_r[h]][a_k[h]]     = __floats2half2_rn(ap[h].x, ap[h].y);
            *(__half2*)&As[a_r[h]][a_k[h] + 2] = __floats2half2_rn(ap[h].z, ap[h].w);
            Bs[b_n[h] + 0][b_k[h]] = __float2half_rn(bp[h].x);
            Bs[b_n[h] + 1][b_k[h]] = __float2half_rn(bp[h].y);
            Bs[b_n[h] + 2][b_k[h]] = __float2half_rn(bp[h].z);
            Bs[b_n[h] + 3][b_k[h]] = __float2half_rn(bp[h].w);
        }
        __syncthreads();

        const int kn = k0 + GBK;
        if (kn < DCOLS) {
#pragma unroll
            for (int h = 0; h < 4; h++) {
                const int grow = row0 + a_r[h];
                ap[h] = make_float4(0.f, 0.f, 0.f, 0.f);
                if (grow < M)
                    ap[h] = *(const float4*)(x + (size_t)grow * DCOLS + kn + a_k[h]);
                bp[h] = *(const float4*)(w + (size_t)(kn + b_k[h]) * DCOLS + col0 + b_n[h]);
            }
        }

#pragma unroll
        for (int ks = 0; ks < 2; ks++) {
            const int kk = ks * 16;
            unsigned a[4][4], b[4][2];
#pragma unroll
            for (int i = 0; i < 4; i++) {
                const int rm = warp_m + i * 16;
                a[i][0] = *(const unsigned*)&As[rm + gid    ][kk + 2 * tig];
                a[i][1] = *(const unsigned*)&As[rm + gid + 8][kk + 2 * tig];
                a[i][2] = *(const unsigned*)&As[rm + gid    ][kk + 8 + 2 * tig];
                a[i][3] = *(const unsigned*)&As[rm + gid + 8][kk + 8 + 2 * tig];
            }
#pragma unroll
            for (int j = 0; j < 4; j++) {
                const int n = warp_n + j * 8 + gid;
                b[j][0] = *(const unsigned*)&Bs[n][kk + 2 * tig];
                b[j][1] = *(const unsigned*)&Bs[n][kk + 8 + 2 * tig];
            }
#pragma unroll
            for (int i = 0; i < 4; i++)
#pragma unroll
                for (int j = 0; j < 4; j++) {
                    asm volatile(
                        "mma.sync.aligned.m16n8k16.row.col.f32.f16.f16.f32 "
                        "{%0,%1,%2,%3}, {%4,%5,%6,%7}, {%8,%9}, {%0,%1,%2,%3};"
                        : "+f"(acc[i][j][0]), "+f"(acc[i][j][1]),
                          "+f"(acc[i][j][2]), "+f"(acc[i][j][3])
                        : "r"(a[i][0]), "r"(a[i][1]), "r"(a[i][2]), "r"(a[i][3]),
                          "r"(b[j][0]), "r"(b[j][1]));
                }
        }
        __syncthreads();
    }

    // epilogue: write fp16 support only
#pragma unroll
    for (int i = 0; i < 4; i++) {
#pragma unroll
        for (int h = 0; h < 2; h++) {
            const int r = row0 + warp_m + i * 16 + gid + h * 8;
            if (r < M) {
#pragma unroll
                for (int j = 0; j < 4; j++) {
                    const int c = col0 + warp_n + j * 8 + 2 * tig;
                    *(__half2*)(g_s16 + (size_t)r * DCOLS + c) =
                        __floats2half2_rn(acc[i][j][2 * h], acc[i][j][2 * h + 1]);
                }
            }
        }
    }
}

// ======================= CSR build =========================================
__global__ void zero_counts_kernel(int M)
{
    for (int i = blockIdx.x * blockDim.x + threadIdx.x; i < M;
         i += gridDim.x * blockDim.x)
        g_counts[i] = 0;
}

__global__ void count_kernel(const int* __restrict__ erow, int E)
{
    const int n4 = E >> 2;
    const int stride = gridDim.x * blockDim.x;
    const int t0 = blockIdx.x * blockDim.x + threadIdx.x;
    for (int i = t0; i < n4; i += stride) {
        int4 r = ((const int4*)erow)[i];
        atomicAdd(&g_counts[r.x], 1);
        atomicAdd(&g_counts[r.y], 1);
        atomicAdd(&g_counts[r.z], 1);
        atomicAdd(&g_counts[r.w], 1);
    }
    if (t0 < (E & 3))
        atomicAdd(&g_counts[erow[(n4 << 2) + t0]], 1);
}

__global__ __launch_bounds__(1024) void local_scan_kernel(int M)
{
    __shared__ int sh[1024];
    const int t = threadIdx.x;
    const int i = blockIdx.x * 1024 + t;
    const int v = (i < M) ? g_counts[i] : 0;
    sh[t] = v;
    __syncthreads();
#pragma unroll
    for (int d = 1; d < 1024; d <<= 1) {
        int u = (t >= d) ? sh[t - d] : 0;
        __syncthreads();
        sh[t] += u;
        __syncthreads();
    }
    if (i < M) g_row_start[i] = sh[t] - v;
    if (t == 1023) g_blocksums[blockIdx.x] = sh[1023];
}

__global__ __launch_bounds__(128) void scan_sums_kernel(int NB)
{
    __shared__ int sh[128];
    const int t = threadIdx.x;
    const int v = (t < NB) ? g_blocksums[t] : 0;
    sh[t] = v;
    __syncthreads();
#pragma unroll
    for (int d = 1; d < 128; d <<= 1) {
        int u = (t >= d) ? sh[t - d] : 0;
        __syncthreads();
        sh[t] += u;
        __syncthreads();
    }
    g_blockoff[t] = sh[t] - v;
}

__global__ __launch_bounds__(1024) void add_off_kernel(int M, int E)
{
    const int t = threadIdx.x;
    const int i = blockIdx.x * 1024 + t;
    if (i < M) {
        const int rs = g_row_start[i] + g_blockoff[blockIdx.x];
        g_row_start[i] = rs;
        g_cursor[i] = rs;
    }
    if (blockIdx.x == 0 && t == 0) g_row_start[M] = E;
}

__device__ __forceinline__ unsigned pack_edge(int col, float w)
{
    unsigned short hb = __half_as_ushort(__float2half_rn(w));
    return ((unsigned)col << 15) | (unsigned)(hb & 0x7FFF);
}

__global__ void scatter_kernel(const int* __restrict__ erow,
                               const int* __restrict__ ecol,
                               const float* __restrict__ ew, int E)
{
    const int n4 = E >> 2;
    const int stride = gridDim.x * blockDim.x;
    const int t0 = blockIdx.x * blockDim.x + threadIdx.x;
    for (int i = t0; i < n4; i += stride) {
        int4   r4 = ((const int4*)erow)[i];
        int4   c4 = ((const int4*)ecol)[i];
        float4 w4 = ((const float4*)ew)[i];
        int p;
        p = atomicAdd(&g_cursor[r4.x], 1); g_csr[p] = pack_edge(c4.x, w4.x);
        p = atomicAdd(&g_cursor[r4.y], 1); g_csr[p] = pack_edge(c4.y, w4.y);
        p = atomicAdd(&g_cursor[r4.z], 1); g_csr[p] = pack_edge(c4.z, w4.z);
        p = atomicAdd(&g_cursor[r4.w], 1); g_csr[p] = pack_edge(c4.w, w4.w);
    }
    if (t0 < (E & 3)) {
        const int i = (n4 << 2) + t0;
        const int pos = atomicAdd(&g_cursor[erow[i]], 1);
        g_csr[pos] = pack_edge(ecol[i], ew[i]);
    }
}

// ======================= fp8 / half helpers ================================
__device__ __forceinline__ __half2 fp8x2_to_h2(unsigned short v)
{
    unsigned r;
    asm("cvt.rn.f16x2.e4m3x2 %0, %1;" : "=r"(r) : "h"(v));
    return *(__half2*)&r;
}

__device__ __forceinline__ unsigned short h2_to_fp8x2(__half2 h)
{
    unsigned short r;
    unsigned u = *(unsigned*)&h;
    asm("cvt.rn.satfinite.e4m3x2.f16x2 %0, %1;" : "=h"(r) : "r"(u));
    return r;
}

__device__ __forceinline__ int edge_col(unsigned word) { return (int)(word >> 15); }
__device__ __forceinline__ __half2 edge_w2(unsigned word)
{
    unsigned u = (word & 0x7FFFu) * 0x00010001u;
    return *(__half2*)&u;
}

__device__ __forceinline__ void acc_h16h(__half2* a, __half2 w2, uint4 v)
{
    const __half2* h = (const __half2*)&v;
#pragma unroll
    for (int q = 0; q < 4; q++)
        a[q] = __hfma2(w2, h[q], a[q]);
}

__device__ __forceinline__ void acc_q8h(__half2* a, __half2 w2, uint2 v)
{
    const unsigned short* p = (const unsigned short*)&v;
#pragma unroll
    for (int q = 0; q < 4; q++)
        a[q] = __hfma2(w2, fp8x2_to_h2(p[q]), a[q]);
}

__device__ __forceinline__ uint4 ldcs4u(const unsigned* p)
{
    uint4 r;
    asm("ld.global.cs.v4.b32 {%0,%1,%2,%3}, [%4];"
        : "=r"(r.x), "=r"(r.y), "=r"(r.z), "=r"(r.w) : "l"(p));
    return r;
}

__device__ __forceinline__ void stcs4(void* p, uint4 v)
{
    asm volatile("st.global.cs.v4.b32 [%0], {%1,%2,%3,%4};"
                 :: "l"(p), "r"(v.x), "r"(v.y), "r"(v.z), "r"(v.w));
}

// ======================= SpMM hops =========================================
// hop1: fp16 gather of s16; writes h1 fp16 (streamed) + h1q fp8(=h1*16)
__global__ __launch_bounds__(256) void spmm1_kernel(int M)
{
    const int warp = (blockIdx.x * blockDim.x + threadIdx.x) >> 5;
    if (warp >= M) return;
    const int lane = threadIdx.x & 31;
    const int s = g_row_start[warp];
    const int e = g_row_start[warp + 1];

    __half2 a[4];
#pragma unroll
    for (int q = 0; q < 4; q++) a[q] = __half2half2(__float2half(0.f));

    int j = s;
    while ((j & 3) && j < e) {
        unsigned c = g_csr[j];
        acc_h16h(a, edge_w2(c), ((const uint4*)(g_s16 + (size_t)edge_col(c) * DCOLS))[lane]);
        j++;
    }
    for (; j + 7 < e; j += 8) {
        uint4 p0 = ldcs4u(&g_csr[j]);
        uint4 p1 = ldcs4u(&g_csr[j + 4]);
        uint4 v0 = ((const uint4*)(g_s16 + (size_t)edge_col(p0.x) * DCOLS))[lane];
        uint4 v1 = ((const uint4*)(g_s16 + (size_t)edge_col(p0.y) * DCOLS))[lane];
        uint4 v2 = ((const uint4*)(g_s16 + (size_t)edge_col(p0.z) * DCOLS))[lane];
        uint4 v3 = ((const uint4*)(g_s16 + (size_t)edge_col(p0.w) * DCOLS))[lane];
        uint4 v4 = ((const uint4*)(g_s16 + (size_t)edge_col(p1.x) * DCOLS))[lane];
        uint4 v5 = ((const uint4*)(g_s16 + (size_t)edge_col(p1.y) * DCOLS))[lane];
        uint4 v6 = ((const uint4*)(g_s16 + (size_t)edge_col(p1.z) * DCOLS))[lane];
        uint4 v7 = ((const uint4*)(g_s16 + (size_t)edge_col(p1.w) * DCOLS))[lane];
        acc_h16h(a, edge_w2(p0.x), v0);
        acc_h16h(a, edge_w2(p0.y), v1);
        acc_h16h(a, edge_w2(p0.z), v2);
        acc_h16h(a, edge_w2(p0.w), v3);
        acc_h16h(a, edge_w2(p1.x), v4);
        acc_h16h(a, edge_w2(p1.y), v5);
        acc_h16h(a, edge_w2(p1.z), v6);
        acc_h16h(a, edge_w2(p1.w), v7);
    }
    for (; j < e; j++) {
        unsigned c = g_csr[j];
        acc_h16h(a, edge_w2(c), ((const uint4*)(g_s16 + (size_t)edge_col(c) * DCOLS))[lane]);
    }

    uint4 o;
    o.x = *(unsigned*)&a[0]; o.y = *(unsigned*)&a[1];
    o.z = *(unsigned*)&a[2]; o.w = *(unsigned*)&a[3];
    stcs4((uint4*)(g_h1 + (size_t)warp * DCOLS) + lane, o);

    const __half2 x16 = __half2half2(__float2half(16.f));
    ushort4 q8;
    q8.x = h2_to_fp8x2(__hmul2(a[0], x16));
    q8.y = h2_to_fp8x2(__hmul2(a[1], x16));
    q8.z = h2_to_fp8x2(__hmul2(a[2], x16));
    q8.w = h2_to_fp8x2(__hmul2(a[3], x16));
    ((ushort4*)(g_h1q + (size_t)warp * DCOLS))[lane] = q8;
}

// hop2: gathers h1q (fp8 = h1*16), half2 accum (a = 16*h2);
// writes h2q fp8(=h2*256 = a*16) ONLY
__global__ __launch_bounds__(256) void spmm2_kernel(int M)
{
    const int warp = (blockIdx.x * blockDim.x + threadIdx.x) >> 5;
    if (warp >= M) return;
    const int lane = threadIdx.x & 31;
    const int s = g_row_start[warp];
    const int e = g_row_start[warp + 1];

    __half2 a[4];
#pragma unroll
    for (int q = 0; q < 4; q++) a[q] = __half2half2(__float2half(0.f));

    int j = s;
    while ((j & 3) && j < e) {
        unsigned c = g_csr[j];
        acc_q8h(a, edge_w2(c), ((const uint2*)(g_h1q + (size_t)edge_col(c) * DCOLS))[lane]);
        j++;
    }
    for (; j + 7 < e; j += 8) {
        uint4 p0 = ldcs4u(&g_csr[j]);
        uint4 p1 = ldcs4u(&g_csr[j + 4]);
        uint2 v0 = ((const uint2*)(g_h1q + (size_t)edge_col(p0.x) * DCOLS))[lane];
        uint2 v1 = ((const uint2*)(g_h1q + (size_t)edge_col(p0.y) * DCOLS))[lane];
        uint2 v2 = ((const uint2*)(g_h1q + (size_t)edge_col(p0.z) * DCOLS))[lane];
        uint2 v3 = ((const uint2*)(g_h1q + (size_t)edge_col(p0.w) * DCOLS))[lane];
        uint2 v4 = ((const uint2*)(g_h1q + (size_t)edge_col(p1.x) * DCOLS))[lane];
        uint2 v5 = ((const uint2*)(g_h1q + (size_t)edge_col(p1.y) * DCOLS))[lane];
        uint2 v6 = ((const uint2*)(g_h1q + (size_t)edge_col(p1.z) * DCOLS))[lane];
        uint2 v7 = ((const uint2*)(g_h1q + (size_t)edge_col(p1.w) * DCOLS))[lane];
        acc_q8h(a, edge_w2(p0.x), v0);
        acc_q8h(a, edge_w2(p0.y), v1);
        acc_q8h(a, edge_w2(p0.z), v2);
        acc_q8h(a, edge_w2(p0.w), v3);
        acc_q8h(a, edge_w2(p1.x), v4);
        acc_q8h(a, edge_w2(p1.y), v5);
        acc_q8h(a, edge_w2(p1.z), v6);
        acc_q8h(a, edge_w2(p1.w), v7);
    }
    for (; j < e; j++) {
        unsigned c = g_csr[j];
        acc_q8h(a, edge_w2(c), ((const uint2*)(g_h1q + (size_t)edge_col(c) * DCOLS))[lane]);
    }

    const __half2 x16 = __half2half2(__float2half(16.f));
    ushort4 q8;
    q8.x = h2_to_fp8x2(__hmul2(a[0], x16));
    q8.y = h2_to_fp8x2(__hmul2(a[1], x16));
    q8.z = h2_to_fp8x2(__hmul2(a[2], x16));
    q8.w = h2_to_fp8x2(__hmul2(a[3], x16));
    ((ushort4*)(g_h2q + (size_t)warp * DCOLS))[lane] = q8;
}

// hop3 fused with combine: out = s16 + h1 + h2q/256 + (A*h2q)/256 + bias
__global__ __launch_bounds__(256) void spmm3_combine_kernel(
    float* __restrict__ out, const float* __restrict__ bias, int M)
{
    const int warp = (blockIdx.x * blockDim.x + threadIdx.x) >> 5;
    if (warp >= M) return;
    const int lane = threadIdx.x & 31;
    const int s = g_row_start[warp];
    const int e = g_row_start[warp + 1];

    __half2 a[4];
#pragma unroll
    for (int q = 0; q < 4; q++) a[q] = __half2half2(__float2half(0.f));

    int j = s;
    while ((j & 3) && j < e) {
        unsigned c = g_csr[j];
        acc_q8h(a, edge_w2(c), ((const uint2*)(g_h2q + (size_t)edge_col(c) * DCOLS))[lane]);
        j++;
    }
    for (; j + 7 < e; j += 8) {
        uint4 p0 = ldcs4u(&g_csr[j]);
        uint4 p1 = ldcs4u(&g_csr[j + 4]);
        uint2 v0 = ((const uint2*)(g_h2q + (size_t)edge_col(p0.x) * DCOLS))[lane];
        uint2 v1 = ((const uint2*)(g_h2q + (size_t)edge_col(p0.y) * DCOLS))[lane];
        uint2 v2 = ((const uint2*)(g_h2q + (size_t)edge_col(p0.z) * DCOLS))[lane];
        uint2 v3 = ((const uint2*)(g_h2q + (size_t)edge_col(p0.w) * DCOLS))[lane];
        uint2 v4 = ((const uint2*)(g_h2q + (size_t)edge_col(p1.x) * DCOLS))[lane];
        uint2 v5 = ((const uint2*)(g_h2q + (size_t)edge_col(p1.y) * DCOLS))[lane];
        uint2 v6 = ((const uint2*)(g_h2q + (size_t)edge_col(p1.z) * DCOLS))[lane];
        uint2 v7 = ((const uint2*)(g_h2q + (size_t)edge_col(p1.w) * DCOLS))[lane];
        acc_q8h(a, edge_w2(p0.x), v0);
        acc_q8h(a, edge_w2(p0.y), v1);
        acc_q8h(a, edge_w2(p0.z), v2);
        acc_q8h(a, edge_w2(p0.w), v3);
        acc_q8h(a, edge_w2(p1.x), v4);
        acc_q8h(a, edge_w2(p1.y), v5);
        acc_q8h(a, edge_w2(p1.z), v6);
        acc_q8h(a, edge_w2(p1.w), v7);
    }
    for (; j < e; j++) {
        unsigned c = g_csr[j];
        acc_q8h(a, edge_w2(c), ((const uint2*)(g_h2q + (size_t)edge_col(c) * DCOLS))[lane]);
    }

    const size_t o = (size_t)warp * DCOLS + lane * 8;
    float4 b0 = *(const float4*)(bias + lane * 8);
    float4 b1 = *(const float4*)(bias + lane * 8 + 4);
    uint4  us = ((const uint4*)(g_s16 + (size_t)warp * DCOLS))[lane];
    uint4  u1 = ((const uint4*)(g_h1 + (size_t)warp * DCOLS))[lane];
    uint2  u2 = ((const uint2*)(g_h2q + (size_t)warp * DCOLS))[lane];
    const __half2* hs = (const __half2*)&us;
    const __half2* h1 = (const __half2*)&u1;
    const unsigned short* q2 = (const unsigned short*)&u2;

    float r[8];
#pragma unroll
    for (int q = 0; q < 4; q++) {
        float2 fs = __half22float2(hs[q]);
        float2 f1 = __half22float2(h1[q]);
        float2 f2 = __half22float2(fp8x2_to_h2(q2[q]));   // = 256 * h2
        float2 f3 = __half22float2(a[q]);                 // = 256 * h3
        r[2 * q + 0] = fs.x + f1.x + (f2.x + f3.x) * (1.f / 256.f);
        r[2 * q + 1] = fs.y + f1.y + (f2.y + f3.y) * (1.f / 256.f);
    }
    float4 o0 = make_float4(r[0] + b0.x, r[1] + b0.y, r[2] + b0.z, r[3] + b0.w);
    float4 o1 = make_float4(r[4] + b1.x, r[5] + b1.y, r[6] + b1.z, r[7] + b1.w);
    stcs4(out + o,     *(uint4*)&o0);
    stcs4(out + o + 4, *(uint4*)&o1);
}

// ======================= launch ============================================
extern "C" void kernel_launch(void* const* d_in, const int* in_sizes, int n_in,
                              void* d_out, int out_size)
{
    const float* x    = (const float*)d_in[0];
    const float* w    = (const float*)d_in[1];
    const float* bias = (const float*)d_in[2];
    const float* ew   = (const float*)d_in[3];
    const int*   er   = (const int*)d_in[4];
    const int*   ec   = (const int*)d_in[5];
    float* out = (float*)d_out;

    const int M = in_sizes[0] / DCOLS;
    const int E = in_sizes[3];
    const int NB = (M + 1023) / 1024;

    cudaStream_t s2;
    cudaEvent_t eFork, eJoin;
    cudaStreamCreateWithFlags(&s2, cudaStreamNonBlocking);
    cudaEventCreateWithFlags(&eFork, cudaEventDisableTiming);
    cudaEventCreateWithFlags(&eJoin, cudaEventDisableTiming);

    cudaEventRecord(eFork, 0);
    cudaStreamWaitEvent(s2, eFork, 0);

    // main stream: fp16 tensor-core GEMM
    dim3 ggrid(DCOLS / GBN, (M + GBM - 1) / GBM);
    gemm_f16_kernel<<<ggrid, 256>>>(x, w, M);

    // side stream: CSR build
    zero_counts_kernel<<<(M + 255) / 256, 256, 0, s2>>>(M);
    count_kernel<<<2048, 256, 0, s2>>>(er, E);
    local_scan_kernel<<<NB, 1024, 0, s2>>>(M);
    scan_sums_kernel<<<1, 128, 0, s2>>>(NB);
    add_off_kernel<<<NB, 1024, 0, s2>>>(M, E);
    scatter_kernel<<<2048, 256, 0, s2>>>(er, ec, ew, E);

    cudaEventRecord(eJoin, s2);
    cudaStreamWaitEvent(0, eJoin, 0);

    // hops
    const int sblocks = (int)(((size_t)M * 32 + 255) / 256);
    spmm1_kernel<<<sblocks, 256>>>(M);
    spmm2_kernel<<<sblocks, 256>>>(M);
    spmm3_combine_kernel<<<sblocks, 256>>>(out, bias, M);

    cudaEventDestroy(eFork);
    cudaEventDestroy(eJoin);
    cudaStreamDestroy(s2);
}